// round 1
// baseline (speedup 1.0000x reference)
#include <cuda_runtime.h>

// Problem constants: B=64, T=4096, D=64, token tile TT=64.
#define AST 65   // activation row stride (floats) -> bank rotation (r+k)%32
#define WST 68   // transposed-weight row stride (floats), 16B-aligned float4 rows

// shared-memory layout (floats)
#define OFF_XS   0                  // x tile      [68][65]
#define OFF_HS   4420               // h tile      [68][65]  (reused as normalized-delta)
#define OFF_WT   8840               // 5 x WtT     [64][68]
#define OFF_PRE  30600              // QP,KP,VP,AP,BP  5 x [68][65]
#define OFF_BIAS 52700              // qb,kb,vb,ab,bb,pb  6 x 64
#define OFF_CW   53084              // qcw,kcw,vcw  3 x 192
#define OFF_CB   53660              // qcb,kcb,vcb  3 x 64
#define OFF_NG   53852              // norm_g 64
#define OFF_PNG  53916              // post_norm_g 64
#define SMEM_FLOATS 53980           // 215,920 bytes

__device__ __forceinline__ float sigm(float z) { return 1.0f / (1.0f + expf(-z)); }

__device__ __forceinline__ float wredsum(float v) {
#pragma unroll
    for (int o = 16; o; o >>= 1) v += __shfl_xor_sync(0xffffffffu, v, o);
    return v;
}

// Matmul: O[r][c] = sum_k A[r][k] * Wt[k][c] + bias[c], rows 0..65, cols 0..63.
// Thread tile: 4 rows x 4 cols. cg = tid&15 (col group), rg = tid>>4 (row group).
// Pass 0 covers rows 0..63; pass 1 (rg==0 only) covers rows 64..65.
// zero_lo/zero_hi force row 0 / row 65 to 0 (conv zero padding at sequence edges).
__device__ __forceinline__ void mm66(const float* __restrict__ A,
                                     const float* __restrict__ Wt,
                                     const float* __restrict__ bias,
                                     float* __restrict__ O,
                                     int cg, int rg, bool zero_lo, bool zero_hi)
{
#pragma unroll
    for (int pass = 0; pass < 2; ++pass) {
        if (pass == 1 && rg != 0) break;
        const int r0 = pass ? 64 : rg * 4;
        float acc[4][4];
#pragma unroll
        for (int i = 0; i < 4; ++i)
#pragma unroll
            for (int j = 0; j < 4; ++j) acc[i][j] = 0.0f;

        const float* a0p = A + r0 * AST;
        const float* wtp = Wt + cg * 4;
#pragma unroll 8
        for (int k = 0; k < 64; ++k) {
            const float4 w = *(const float4*)(wtp + k * WST);
            const float a0 = a0p[k];
            const float a1 = a0p[AST + k];
            const float a2 = a0p[2 * AST + k];
            const float a3 = a0p[3 * AST + k];
            acc[0][0] += a0 * w.x; acc[0][1] += a0 * w.y; acc[0][2] += a0 * w.z; acc[0][3] += a0 * w.w;
            acc[1][0] += a1 * w.x; acc[1][1] += a1 * w.y; acc[1][2] += a1 * w.z; acc[1][3] += a1 * w.w;
            acc[2][0] += a2 * w.x; acc[2][1] += a2 * w.y; acc[2][2] += a2 * w.z; acc[2][3] += a2 * w.w;
            acc[3][0] += a3 * w.x; acc[3][1] += a3 * w.y; acc[3][2] += a3 * w.z; acc[3][3] += a3 * w.w;
        }
#pragma unroll
        for (int rr = 0; rr < 4; ++rr) {
            const int r = r0 + rr;
            if (r >= 66) break;
            const bool z = (zero_lo && r == 0) || (zero_hi && r == 65);
#pragma unroll
            for (int cc = 0; cc < 4; ++cc) {
                const int c = cg * 4 + cc;
                O[r * AST + c] = z ? 0.0f : (acc[rr][cc] + bias[c]);
            }
        }
    }
}

__global__ void __launch_bounds__(256, 1) gdn_kernel(
    const float* __restrict__ x,   const float* __restrict__ norm_g,
    const float* __restrict__ qw,  const float* __restrict__ qb,
    const float* __restrict__ kw,  const float* __restrict__ kb,
    const float* __restrict__ vw,  const float* __restrict__ vb,
    const float* __restrict__ qcw, const float* __restrict__ qcb,
    const float* __restrict__ kcw, const float* __restrict__ kcb,
    const float* __restrict__ vcw, const float* __restrict__ vcb,
    const float* __restrict__ aw,  const float* __restrict__ ab,
    const float* __restrict__ bw,  const float* __restrict__ bb,
    const float* __restrict__ png, const float* __restrict__ pw,
    const float* __restrict__ pb,  float* __restrict__ out)
{
    extern __shared__ float sm[];
    float* XS   = sm + OFF_XS;
    float* HS   = sm + OFF_HS;
    float* WT   = sm + OFF_WT;
    float* PRE  = sm + OFF_PRE;
    float* BIAS = sm + OFF_BIAS;
    float* CW   = sm + OFF_CW;
    float* CB   = sm + OFF_CB;
    float* NG   = sm + OFF_NG;
    float* PNG  = sm + OFF_PNG;

    const int tid = threadIdx.x;
    const int b   = blockIdx.x >> 6;
    const int t0  = (blockIdx.x & 63) << 6;
    const long xbase = ((long)b * 4096 + t0) * 64;

    // ---- load x tile, rows 0..65 <-> tokens t0-1 .. t0+64 (zero out-of-range) ----
    for (int idx = tid; idx < 66 * 64; idx += 256) {
        const int r = idx >> 6, c = idx & 63;
        const int gt = t0 - 1 + r;
        float v = 0.0f;
        if (gt >= 0 && gt < 4096) v = x[((long)b * 4096 + gt) * 64 + c];
        XS[r * AST + c] = v;
    }

    // ---- load 5 weight matrices transposed: Wt[k][c] = W[c][k] ----
    {
        const float* wsrc[5] = { qw, kw, vw, aw, bw };
#pragma unroll
        for (int m = 0; m < 5; ++m) {
            const float* W = wsrc[m];
            float* Wt = WT + m * (64 * WST);
            for (int idx = tid; idx < 4096; idx += 256) {
                const int c = idx >> 6, k = idx & 63;
                Wt[k * WST + c] = W[idx];   // coalesced global read
            }
        }
    }
    if (tid < 64) {
        BIAS[tid]       = qb[tid];  BIAS[64 + tid]  = kb[tid];  BIAS[128 + tid] = vb[tid];
        BIAS[192 + tid] = ab[tid];  BIAS[256 + tid] = bb[tid];  BIAS[320 + tid] = pb[tid];
        CB[tid] = qcb[tid];  CB[64 + tid] = kcb[tid];  CB[128 + tid] = vcb[tid];
        NG[tid] = norm_g[tid];  PNG[tid] = png[tid];
    }
    if (tid < 192) { CW[tid] = qcw[tid]; CW[192 + tid] = kcw[tid]; CW[384 + tid] = vcw[tid]; }
    __syncthreads();

    // ---- zc_rmsnorm(x) -> HS, warp per row ----
    {
        const int warp = tid >> 5, lane = tid & 31;
        for (int r = warp; r < 66; r += 8) {
            const float a = XS[r * AST + lane];
            const float bvv = XS[r * AST + lane + 32];
            const float mean = wredsum(a + bvv) * (1.0f / 64.0f);
            const float a0 = a - mean, b0 = bvv - mean;
            const float ms = wredsum(a0 * a0 + b0 * b0) * (1.0f / 64.0f);
            const float inv = rsqrtf(ms + 1e-8f);
            HS[r * AST + lane]      = a0 * inv * NG[lane];
            HS[r * AST + lane + 32] = b0 * inv * NG[lane + 32];
        }
    }
    __syncthreads();

    // ---- phase-1 matmuls: QP/KP/VP from H, AP/BP from x ----
    const int cg = tid & 15, rg = tid >> 4;
    const bool zlo = (t0 == 0), zhi = (t0 + 64 == 4096);
    mm66(HS, WT + 0 * (64 * WST), BIAS + 0,   PRE + 0 * 4420, cg, rg, zlo, zhi);
    mm66(HS, WT + 1 * (64 * WST), BIAS + 64,  PRE + 1 * 4420, cg, rg, zlo, zhi);
    mm66(HS, WT + 2 * (64 * WST), BIAS + 128, PRE + 2 * 4420, cg, rg, zlo, zhi);
    mm66(XS, WT + 3 * (64 * WST), BIAS + 192, PRE + 3 * 4420, cg, rg, false, false);
    mm66(XS, WT + 4 * (64 * WST), BIAS + 256, PRE + 4 * 4420, cg, rg, false, false);
    __syncthreads();

    // ---- load pw transposed into weight slot 0 (qw dead now) ----
    for (int idx = tid; idx < 4096; idx += 256) {
        const int c = idx >> 6, k = idx & 63;
        WT[k * WST + c] = pw[idx];
    }

    // ---- per-token stage: conv3 + sigmoid + l2norm + delta + gate + zc_rmsnorm ----
    {
        const int warp = tid >> 5, lane = tid & 31;
        const float* QP = PRE;
        const float* KP = PRE + 4420;
        const float* VP = PRE + 2 * 4420;
        const float* AP = PRE + 3 * 4420;
        const float* BP = PRE + 4 * 4420;
        for (int j = 1 + warp; j < 65; j += 8) {   // array row j <-> token t0 + j - 1
            float qv[2], kv[2], vv[2];
#pragma unroll
            for (int h = 0; h < 2; ++h) {
                const int c = lane + 32 * h;
                const float qm = QP[(j - 1) * AST + c], q0 = QP[j * AST + c], qp = QP[(j + 1) * AST + c];
                qv[h] = sigm(CW[c * 3 + 0] * qm + CW[c * 3 + 1] * q0 + CW[c * 3 + 2] * qp + CB[c]);
                const float km = KP[(j - 1) * AST + c], k0 = KP[j * AST + c], kp = KP[(j + 1) * AST + c];
                kv[h] = sigm(CW[192 + c * 3 + 0] * km + CW[192 + c * 3 + 1] * k0 + CW[192 + c * 3 + 2] * kp + CB[64 + c]);
                const float vm = VP[(j - 1) * AST + c], v0 = VP[j * AST + c], vp = VP[(j + 1) * AST + c];
                vv[h] = sigm(CW[384 + c * 3 + 0] * vm + CW[384 + c * 3 + 1] * v0 + CW[384 + c * 3 + 2] * vp + CB[128 + c]);
            }
            const float qi = rsqrtf(wredsum(qv[0] * qv[0] + qv[1] * qv[1]) + 1e-8f);
            const float ki = rsqrtf(wredsum(kv[0] * kv[0] + kv[1] * kv[1]) + 1e-8f);
            float d2[2];
#pragma unroll
            for (int h = 0; h < 2; ++h) {
                const int c = lane + 32 * h;
                const float delta = (qv[h] * qi) * ((kv[h] * ki) * vv[h]);
                d2[h] = tanhf(AP[j * AST + c]) * delta + BP[j * AST + c];
            }
            const float mean = wredsum(d2[0] + d2[1]) * (1.0f / 64.0f);
            const float e0 = d2[0] - mean, e1 = d2[1] - mean;
            const float ms = wredsum(e0 * e0 + e1 * e1) * (1.0f / 64.0f);
            const float inv = rsqrtf(ms + 1e-8f);
            HS[(j - 1) * AST + lane]      = e0 * inv * PNG[lane];
            HS[(j - 1) * AST + lane + 32] = e1 * inv * PNG[lane + 32];
        }
    }
    __syncthreads();

    // ---- final matmul (pw) + gating epilogue, coalesced float4 stores ----
    {
        const int r0 = rg * 4;
        float acc[4][4];
#pragma unroll
        for (int i = 0; i < 4; ++i)
#pragma unroll
            for (int j = 0; j < 4; ++j) acc[i][j] = 0.0f;

        const float* a0p = HS + r0 * AST;
        const float* wtp = WT + cg * 4;
#pragma unroll 8
        for (int k = 0; k < 64; ++k) {
            const float4 w = *(const float4*)(wtp + k * WST);
            const float a0 = a0p[k];
            const float a1 = a0p[AST + k];
            const float a2 = a0p[2 * AST + k];
            const float a3 = a0p[3 * AST + k];
            acc[0][0] += a0 * w.x; acc[0][1] += a0 * w.y; acc[0][2] += a0 * w.z; acc[0][3] += a0 * w.w;
            acc[1][0] += a1 * w.x; acc[1][1] += a1 * w.y; acc[1][2] += a1 * w.z; acc[1][3] += a1 * w.w;
            acc[2][0] += a2 * w.x; acc[2][1] += a2 * w.y; acc[2][2] += a2 * w.z; acc[2][3] += a2 * w.w;
            acc[3][0] += a3 * w.x; acc[3][1] += a3 * w.y; acc[3][2] += a3 * w.z; acc[3][3] += a3 * w.w;
        }
#pragma unroll
        for (int rr = 0; rr < 4; ++rr) {
            const int r = r0 + rr;           // token t0 + r
            float4 o4;
            float* op = (float*)&o4;
#pragma unroll
            for (int cc = 0; cc < 4; ++cc) {
                const int c = cg * 4 + cc;
                const float dhat = acc[rr][cc] + BIAS[320 + c];
                const float sil  = dhat * sigm(dhat);         // silu
                const float gate = sigm(sil);                 // sigmoid(silu(dhat))
                const float xv   = XS[(r + 1) * AST + c];     // residual x
                op[cc] = xv + gate * dhat;
            }
            *(float4*)(out + xbase + (long)r * 64 + cg * 4) = o4;
        }
    }
}

extern "C" void kernel_launch(void* const* d_in, const int* in_sizes, int n_in,
                              void* d_out, int out_size)
{
    const float* x      = (const float*)d_in[0];
    const float* norm_g = (const float*)d_in[1];
    const float* qw  = (const float*)d_in[2];
    const float* qb  = (const float*)d_in[3];
    const float* kw  = (const float*)d_in[4];
    const float* kb  = (const float*)d_in[5];
    const float* vw  = (const float*)d_in[6];
    const float* vb  = (const float*)d_in[7];
    const float* qcw = (const float*)d_in[8];
    const float* qcb = (const float*)d_in[9];
    const float* kcw = (const float*)d_in[10];
    const float* kcb = (const float*)d_in[11];
    const float* vcw = (const float*)d_in[12];
    const float* vcb = (const float*)d_in[13];
    const float* aw  = (const float*)d_in[14];
    const float* ab  = (const float*)d_in[15];
    const float* bw  = (const float*)d_in[16];
    const float* bb  = (const float*)d_in[17];
    const float* png = (const float*)d_in[18];
    const float* pw  = (const float*)d_in[19];
    const float* pb  = (const float*)d_in[20];
    float* out = (float*)d_out;

    const int smem_bytes = SMEM_FLOATS * (int)sizeof(float);
    cudaFuncSetAttribute(gdn_kernel, cudaFuncAttributeMaxDynamicSharedMemorySize, smem_bytes);
    gdn_kernel<<<4096, 256, smem_bytes>>>(
        x, norm_g, qw, qb, kw, kb, vw, vb, qcw, qcb, kcw, kcb, vcw, vcb,
        aw, ab, bw, bb, png, pw, pb, out);
}

// round 2
// speedup vs baseline: 1.3535x; 1.3535x over previous
#include <cuda_runtime.h>

// Problem constants: B=64, T=4096, D=64, token tile TT=64.
#define AST 64   // activation row stride (floats), 16B-aligned rows for float4 LDS
#define WST 68   // transposed-weight row stride (floats), 16B-aligned float4 rows

// shared-memory layout (floats)
#define OFF_XS   0                   // x tile      [66][64]
#define OFF_HS   4224                // h tile      [66][64]  (reused as normalized-delta)
#define OFF_WT   8448                // 5 x WtT     [64][68]
#define OFF_PRE  30208               // QP,KP,VP,AP,BP  5 x [66][64]
#define OFF_BIAS 51328               // qb,kb,vb,ab,bb,pb  6 x 64
#define OFF_CW   51712               // qcw,kcw,vcw  3 x 192
#define OFF_CB   52288               // qcb,kcb,vcb  3 x 64
#define OFF_NG   52480               // norm_g 64
#define OFF_PNG  52544               // post_norm_g 64
#define SMEM_FLOATS 52608            // 210,432 bytes

#define FMA4(accr, aval, wv) \
    accr[0] = fmaf(aval, wv.x, accr[0]); \
    accr[1] = fmaf(aval, wv.y, accr[1]); \
    accr[2] = fmaf(aval, wv.z, accr[2]); \
    accr[3] = fmaf(aval, wv.w, accr[3]);

__device__ __forceinline__ float sigm(float z) { return 1.0f / (1.0f + expf(-z)); }

__device__ __forceinline__ float wredsum(float v) {
#pragma unroll
    for (int o = 16; o; o >>= 1) v += __shfl_xor_sync(0xffffffffu, v, o);
    return v;
}

// Matmul: O[r][c] = sum_k A[r][k] * Wt[k][c] + bias[c], rows 0..65, cols 0..63.
// 512 threads. Thread tile: 2 rows x 4 cols. cg = tid&15, rg = tid>>4 (0..31).
// Pass 0 covers rows 0..63; pass 1 (rg==0 only) covers rows 64..65.
// zero_lo/zero_hi force row 0 / row 65 to 0 (conv zero padding at sequence edges).
__device__ __forceinline__ void mm66v(const float* __restrict__ A,
                                      const float* __restrict__ Wt,
                                      const float* __restrict__ bias,
                                      float* __restrict__ O,
                                      int cg, int rg, bool zero_lo, bool zero_hi)
{
#pragma unroll
    for (int pass = 0; pass < 2; ++pass) {
        if (pass == 1 && rg != 0) break;
        const int r0 = pass ? 64 : rg * 2;
        float acc0[4] = {0.f, 0.f, 0.f, 0.f};
        float acc1[4] = {0.f, 0.f, 0.f, 0.f};

        const float* ap = A + r0 * AST;
        const float* wp = Wt + cg * 4;
#pragma unroll 4
        for (int k = 0; k < 64; k += 4) {
            const float4 a0 = *(const float4*)(ap + k);
            const float4 a1 = *(const float4*)(ap + AST + k);
            const float4 w0 = *(const float4*)(wp + (k + 0) * WST);
            const float4 w1 = *(const float4*)(wp + (k + 1) * WST);
            const float4 w2 = *(const float4*)(wp + (k + 2) * WST);
            const float4 w3 = *(const float4*)(wp + (k + 3) * WST);
            FMA4(acc0, a0.x, w0); FMA4(acc0, a0.y, w1);
            FMA4(acc0, a0.z, w2); FMA4(acc0, a0.w, w3);
            FMA4(acc1, a1.x, w0); FMA4(acc1, a1.y, w1);
            FMA4(acc1, a1.z, w2); FMA4(acc1, a1.w, w3);
        }
        const float4 bv = *(const float4*)(bias + cg * 4);
#pragma unroll
        for (int rr = 0; rr < 2; ++rr) {
            const int r = r0 + rr;
            const bool z = (zero_lo && r == 0) || (zero_hi && r == 65);
            const float* acc = rr ? acc1 : acc0;
            float4 o;
            o.x = z ? 0.f : acc[0] + bv.x;
            o.y = z ? 0.f : acc[1] + bv.y;
            o.z = z ? 0.f : acc[2] + bv.z;
            o.w = z ? 0.f : acc[3] + bv.w;
            *(float4*)(O + r * AST + cg * 4) = o;
        }
    }
}

__global__ void __launch_bounds__(512, 1) gdn_kernel(
    const float* __restrict__ x,   const float* __restrict__ norm_g,
    const float* __restrict__ qw,  const float* __restrict__ qb,
    const float* __restrict__ kw,  const float* __restrict__ kb,
    const float* __restrict__ vw,  const float* __restrict__ vb,
    const float* __restrict__ qcw, const float* __restrict__ qcb,
    const float* __restrict__ kcw, const float* __restrict__ kcb,
    const float* __restrict__ vcw, const float* __restrict__ vcb,
    const float* __restrict__ aw,  const float* __restrict__ ab,
    const float* __restrict__ bw,  const float* __restrict__ bb,
    const float* __restrict__ png, const float* __restrict__ pw,
    const float* __restrict__ pb,  float* __restrict__ out)
{
    extern __shared__ float sm[];
    float* XS   = sm + OFF_XS;
    float* HS   = sm + OFF_HS;
    float* WT   = sm + OFF_WT;
    float* PRE  = sm + OFF_PRE;
    float* BIAS = sm + OFF_BIAS;
    float* CW   = sm + OFF_CW;
    float* CB   = sm + OFF_CB;
    float* NG   = sm + OFF_NG;
    float* PNG  = sm + OFF_PNG;

    const int tid = threadIdx.x;
    const int b   = blockIdx.x >> 6;
    const int t0  = (blockIdx.x & 63) << 6;
    const long xbase = ((long)b * 4096 + t0) * 64;

    // ---- load x tile (float4), rows 0..65 <-> tokens t0-1 .. t0+64 ----
    for (int idx = tid; idx < 66 * 16; idx += 512) {
        const int r = idx >> 4, c4 = idx & 15;
        const int gt = t0 - 1 + r;
        float4 v = make_float4(0.f, 0.f, 0.f, 0.f);
        if (gt >= 0 && gt < 4096)
            v = *(const float4*)(x + ((long)b * 4096 + gt) * 64 + c4 * 4);
        *(float4*)(XS + r * AST + c4 * 4) = v;
    }

    // ---- load 5 weight matrices transposed: Wt[k][c] = W[c][k] ----
    {
        const float* wsrc[5] = { qw, kw, vw, aw, bw };
#pragma unroll
        for (int m = 0; m < 5; ++m) {
            const float* W = wsrc[m];
            float* Wt = WT + m * (64 * WST);
            for (int idx = tid; idx < 4096; idx += 512) {
                const int c = idx >> 6, k = idx & 63;
                Wt[k * WST + c] = W[idx];   // coalesced global read
            }
        }
    }
    if (tid < 64) {
        BIAS[tid]       = qb[tid];  BIAS[64 + tid]  = kb[tid];  BIAS[128 + tid] = vb[tid];
        BIAS[192 + tid] = ab[tid];  BIAS[256 + tid] = bb[tid];  BIAS[320 + tid] = pb[tid];
        CB[tid] = qcb[tid];  CB[64 + tid] = kcb[tid];  CB[128 + tid] = vcb[tid];
        NG[tid] = norm_g[tid];  PNG[tid] = png[tid];
    }
    if (tid >= 64 && tid < 256) {
        const int i = tid - 64;
        CW[i] = qcw[i]; CW[192 + i] = kcw[i]; CW[384 + i] = vcw[i];
    }
    __syncthreads();

    // ---- zc_rmsnorm(x) -> HS, warp per row ----
    {
        const int warp = tid >> 5, lane = tid & 31;
        for (int r = warp; r < 66; r += 16) {
            const float a = XS[r * AST + lane];
            const float bvv = XS[r * AST + lane + 32];
            const float mean = wredsum(a + bvv) * (1.0f / 64.0f);
            const float a0 = a - mean, b0 = bvv - mean;
            const float ms = wredsum(a0 * a0 + b0 * b0) * (1.0f / 64.0f);
            const float inv = rsqrtf(ms + 1e-8f);
            HS[r * AST + lane]      = a0 * inv * NG[lane];
            HS[r * AST + lane + 32] = b0 * inv * NG[lane + 32];
        }
    }
    __syncthreads();

    // ---- phase-1 matmuls: QP/KP/VP from H, AP/BP from x ----
    const int cg = tid & 15, rg = tid >> 4;
    const bool zlo = (t0 == 0), zhi = (t0 + 64 == 4096);
    mm66v(HS, WT + 0 * (64 * WST), BIAS + 0,   PRE + 0 * 4224, cg, rg, zlo, zhi);
    mm66v(HS, WT + 1 * (64 * WST), BIAS + 64,  PRE + 1 * 4224, cg, rg, zlo, zhi);
    mm66v(HS, WT + 2 * (64 * WST), BIAS + 128, PRE + 2 * 4224, cg, rg, zlo, zhi);
    mm66v(XS, WT + 3 * (64 * WST), BIAS + 192, PRE + 3 * 4224, cg, rg, false, false);
    mm66v(XS, WT + 4 * (64 * WST), BIAS + 256, PRE + 4 * 4224, cg, rg, false, false);
    __syncthreads();

    // ---- load pw transposed into weight slot 0 (qw dead now) ----
    for (int idx = tid; idx < 4096; idx += 512) {
        const int c = idx >> 6, k = idx & 63;
        WT[k * WST + c] = pw[idx];
    }

    // ---- per-token stage: conv3 + sigmoid + l2norm + delta + gate + zc_rmsnorm ----
    {
        const int warp = tid >> 5, lane = tid & 31;
        const float* QP = PRE;
        const float* KP = PRE + 4224;
        const float* VP = PRE + 2 * 4224;
        const float* AP = PRE + 3 * 4224;
        const float* BP = PRE + 4 * 4224;
        for (int j = 1 + warp; j < 65; j += 16) {  // array row j <-> token t0 + j - 1
            float qv[2], kv[2], vv[2];
#pragma unroll
            for (int h = 0; h < 2; ++h) {
                const int c = lane + 32 * h;
                const float qm = QP[(j - 1) * AST + c], q0 = QP[j * AST + c], qp = QP[(j + 1) * AST + c];
                qv[h] = sigm(CW[c * 3 + 0] * qm + CW[c * 3 + 1] * q0 + CW[c * 3 + 2] * qp + CB[c]);
                const float km = KP[(j - 1) * AST + c], k0 = KP[j * AST + c], kp = KP[(j + 1) * AST + c];
                kv[h] = sigm(CW[192 + c * 3 + 0] * km + CW[192 + c * 3 + 1] * k0 + CW[192 + c * 3 + 2] * kp + CB[64 + c]);
                const float vm = VP[(j - 1) * AST + c], v0 = VP[j * AST + c], vp = VP[(j + 1) * AST + c];
                vv[h] = sigm(CW[384 + c * 3 + 0] * vm + CW[384 + c * 3 + 1] * v0 + CW[384 + c * 3 + 2] * vp + CB[128 + c]);
            }
            const float qi = rsqrtf(wredsum(qv[0] * qv[0] + qv[1] * qv[1]) + 1e-8f);
            const float ki = rsqrtf(wredsum(kv[0] * kv[0] + kv[1] * kv[1]) + 1e-8f);
            float d2[2];
#pragma unroll
            for (int h = 0; h < 2; ++h) {
                const int c = lane + 32 * h;
                const float delta = (qv[h] * qi) * ((kv[h] * ki) * vv[h]);
                d2[h] = tanhf(AP[j * AST + c]) * delta + BP[j * AST + c];
            }
            const float mean = wredsum(d2[0] + d2[1]) * (1.0f / 64.0f);
            const float e0 = d2[0] - mean, e1 = d2[1] - mean;
            const float ms = wredsum(e0 * e0 + e1 * e1) * (1.0f / 64.0f);
            const float inv = rsqrtf(ms + 1e-8f);
            HS[(j - 1) * AST + lane]      = e0 * inv * PNG[lane];
            HS[(j - 1) * AST + lane + 32] = e1 * inv * PNG[lane + 32];
        }
    }
    __syncthreads();

    // ---- final matmul (pw) + gating epilogue, coalesced float4 stores ----
    {
        const int r0 = rg * 2;   // rows 0..63 covered by rg 0..31
        float acc0[4] = {0.f, 0.f, 0.f, 0.f};
        float acc1[4] = {0.f, 0.f, 0.f, 0.f};
        const float* ap = HS + r0 * AST;
        const float* wp = WT + cg * 4;
#pragma unroll 4
        for (int k = 0; k < 64; k += 4) {
            const float4 a0 = *(const float4*)(ap + k);
            const float4 a1 = *(const float4*)(ap + AST + k);
            const float4 w0 = *(const float4*)(wp + (k + 0) * WST);
            const float4 w1 = *(const float4*)(wp + (k + 1) * WST);
            const float4 w2 = *(const float4*)(wp + (k + 2) * WST);
            const float4 w3 = *(const float4*)(wp + (k + 3) * WST);
            FMA4(acc0, a0.x, w0); FMA4(acc0, a0.y, w1);
            FMA4(acc0, a0.z, w2); FMA4(acc0, a0.w, w3);
            FMA4(acc1, a1.x, w0); FMA4(acc1, a1.y, w1);
            FMA4(acc1, a1.z, w2); FMA4(acc1, a1.w, w3);
        }
        const float4 bv = *(const float4*)(BIAS + 320 + cg * 4);
        const float bvv[4] = { bv.x, bv.y, bv.z, bv.w };
#pragma unroll
        for (int rr = 0; rr < 2; ++rr) {
            const int r = r0 + rr;            // token t0 + r
            const float* acc = rr ? acc1 : acc0;
            float4 o4;
            float* op = (float*)&o4;
#pragma unroll
            for (int cc = 0; cc < 4; ++cc) {
                const float dhat = acc[cc] + bvv[cc];
                const float sil  = dhat * sigm(dhat);   // silu
                const float gate = sigm(sil);           // sigmoid(silu(dhat))
                const float xv   = XS[(r + 1) * AST + cg * 4 + cc];  // residual x
                op[cc] = xv + gate * dhat;
            }
            *(float4*)(out + xbase + (long)r * 64 + cg * 4) = o4;
        }
    }
}

extern "C" void kernel_launch(void* const* d_in, const int* in_sizes, int n_in,
                              void* d_out, int out_size)
{
    const float* x      = (const float*)d_in[0];
    const float* norm_g = (const float*)d_in[1];
    const float* qw  = (const float*)d_in[2];
    const float* qb  = (const float*)d_in[3];
    const float* kw  = (const float*)d_in[4];
    const float* kb  = (const float*)d_in[5];
    const float* vw  = (const float*)d_in[6];
    const float* vb  = (const float*)d_in[7];
    const float* qcw = (const float*)d_in[8];
    const float* qcb = (const float*)d_in[9];
    const float* kcw = (const float*)d_in[10];
    const float* kcb = (const float*)d_in[11];
    const float* vcw = (const float*)d_in[12];
    const float* vcb = (const float*)d_in[13];
    const float* aw  = (const float*)d_in[14];
    const float* ab  = (const float*)d_in[15];
    const float* bw  = (const float*)d_in[16];
    const float* bb  = (const float*)d_in[17];
    const float* png = (const float*)d_in[18];
    const float* pw  = (const float*)d_in[19];
    const float* pb  = (const float*)d_in[20];
    float* out = (float*)d_out;

    const int smem_bytes = SMEM_FLOATS * (int)sizeof(float);
    cudaFuncSetAttribute(gdn_kernel, cudaFuncAttributeMaxDynamicSharedMemorySize, smem_bytes);
    gdn_kernel<<<4096, 512, smem_bytes>>>(
        x, norm_g, qw, qb, kw, kb, vw, vb, qcw, qcb, kcw, kcb, vcw, vcb,
        aw, ab, bw, bb, png, pw, pb, out);
}

// round 3
// speedup vs baseline: 2.2546x; 1.6657x over previous
#include <cuda_runtime.h>
#include <cstdint>

// B=64, T=4096, D=64, token tile 64 (+2 halo rows), M padded to 80 for m16 tiles.
#define AST 68            // activation row stride (floats): (4g+c)%32 unique for frag loads
#define WST 72            // weight row stride: (8tg+g)%32 unique for B-frag loads
#define WSLOT (64 * 72)   // one transposed weight matrix
#define PSLOT (66 * 68)   // one preactivation buffer

// shared memory layout (floats)
#define OFF_XS   0                 // [80][68]
#define OFF_HS   5440              // [80][68]
#define OFF_WT   10880             // 5 x [64][72]
#define OFF_PRE  33920             // 5 x [66][68]
#define OFF_BIAS 56360             // qb,kb,vb,ab,bb,pb : 6 x 64
#define OFF_CW   56744             // qcw,kcw,vcw : 3 x 192
#define OFF_CB   57320             // qcb,kcb,vcb : 3 x 64
#define OFF_NG   57512
#define OFF_PNG  57576
#define SMEM_FLOATS 57640          // 230,560 bytes

__device__ __forceinline__ float sigm(float z) { return 1.0f / (1.0f + expf(-z)); }

__device__ __forceinline__ float wredsum(float v) {
#pragma unroll
    for (int o = 16; o; o >>= 1) v += __shfl_xor_sync(0xffffffffu, v, o);
    return v;
}

__device__ __forceinline__ unsigned f2tf(float f) {
    unsigned u;
    asm("cvt.rna.tf32.f32 %0, %1;" : "=r"(u) : "f"(f));
    return u;
}

__device__ __forceinline__ void mma8(float* d, unsigned a0, unsigned a1, unsigned a2, unsigned a3,
                                     unsigned b0, unsigned b1) {
    asm("mma.sync.aligned.m16n8k8.row.col.f32.tf32.tf32.f32 "
        "{%0,%1,%2,%3}, {%4,%5,%6,%7}, {%8,%9}, {%0,%1,%2,%3};"
        : "+f"(d[0]), "+f"(d[1]), "+f"(d[2]), "+f"(d[3])
        : "r"(a0), "r"(a1), "r"(a2), "r"(a3), "r"(b0), "r"(b1));
}

__global__ void __launch_bounds__(512, 1) gdn_kernel(
    const float* __restrict__ x,   const float* __restrict__ norm_g,
    const float* __restrict__ qw,  const float* __restrict__ qb,
    const float* __restrict__ kw,  const float* __restrict__ kb,
    const float* __restrict__ vw,  const float* __restrict__ vb,
    const float* __restrict__ qcw, const float* __restrict__ qcb,
    const float* __restrict__ kcw, const float* __restrict__ kcb,
    const float* __restrict__ vcw, const float* __restrict__ vcb,
    const float* __restrict__ aw,  const float* __restrict__ ab,
    const float* __restrict__ bw,  const float* __restrict__ bb,
    const float* __restrict__ png, const float* __restrict__ pw,
    const float* __restrict__ pb,  float* __restrict__ out)
{
    extern __shared__ float sm[];
    float* XS   = sm + OFF_XS;
    float* HS   = sm + OFF_HS;
    float* WT   = sm + OFF_WT;
    float* PRE  = sm + OFF_PRE;
    float* BIAS = sm + OFF_BIAS;
    float* CW   = sm + OFF_CW;
    float* CB   = sm + OFF_CB;
    float* NG   = sm + OFF_NG;
    float* PNG  = sm + OFF_PNG;

    const int tid  = threadIdx.x;
    const int warp = tid >> 5;
    const int lane = tid & 31;
    const int g    = lane >> 2;    // mma group id (0..7)
    const int tg   = lane & 3;     // mma thread-in-group (0..3)
    const int b    = blockIdx.x >> 6;
    const int t0   = (blockIdx.x & 63) << 6;
    const long xbase = ((long)b * 4096 + t0) * 64;
    const bool zlo = (t0 == 0), zhi = (t0 + 64 == 4096);

    // ---- load x tile rows 0..65 <-> tokens t0-1..t0+64; rows 66..79 zero ----
    for (int idx = tid; idx < 80 * 16; idx += 512) {
        const int r = idx >> 4, c4 = idx & 15;
        const int gt = t0 - 1 + r;
        float4 v = make_float4(0.f, 0.f, 0.f, 0.f);
        if (r < 66 && gt >= 0 && gt < 4096)
            v = *(const float4*)(x + ((long)b * 4096 + gt) * 64 + c4 * 4);
        *(float4*)(XS + r * AST + c4 * 4) = v;
    }

    // ---- transpose 5 weight matrices into WT (tf32), conflict-free STS ----
    {
        const float* wsrc[5] = { qw, kw, vw, aw, bw };
        for (int idx = tid; idx < 5 * 1024; idx += 512) {
            const int m  = idx >> 10;
            const int rm = idx & 1023;
            const int c  = rm & 63;
            const int k4 = rm >> 6;          // 0..15
            const float4 w4 = *(const float4*)(wsrc[m] + c * 64 + k4 * 4);
            float* dst = WT + m * WSLOT + c;
            dst[(4 * k4 + 0) * WST] = __uint_as_float(f2tf(w4.x));
            dst[(4 * k4 + 1) * WST] = __uint_as_float(f2tf(w4.y));
            dst[(4 * k4 + 2) * WST] = __uint_as_float(f2tf(w4.z));
            dst[(4 * k4 + 3) * WST] = __uint_as_float(f2tf(w4.w));
        }
    }
    if (tid < 64) {
        BIAS[tid]       = qb[tid];  BIAS[64 + tid]  = kb[tid];  BIAS[128 + tid] = vb[tid];
        BIAS[192 + tid] = ab[tid];  BIAS[256 + tid] = bb[tid];  BIAS[320 + tid] = pb[tid];
        CB[tid] = qcb[tid];  CB[64 + tid] = kcb[tid];  CB[128 + tid] = vcb[tid];
        NG[tid] = norm_g[tid];  PNG[tid] = png[tid];
    }
    if (tid >= 64 && tid < 256) {
        const int i = tid - 64;
        CW[i] = qcw[i]; CW[192 + i] = kcw[i]; CW[384 + i] = vcw[i];
    }
    __syncthreads();

    // ---- zc_rmsnorm(x) -> HS (rows 66..79 become zero automatically) ----
    for (int r = warp; r < 80; r += 16) {
        const float a  = XS[r * AST + lane];
        const float bv = XS[r * AST + lane + 32];
        const float mean = wredsum(a + bv) * (1.0f / 64.0f);
        const float a0 = a - mean, b0 = bv - mean;
        const float ms = wredsum(a0 * a0 + b0 * b0) * (1.0f / 64.0f);
        const float inv = rsqrtf(ms + 1e-8f);
        HS[r * AST + lane]      = a0 * inv * NG[lane];
        HS[r * AST + lane + 32] = b0 * inv * NG[lane + 32];
    }
    __syncthreads();

    // ---- phase-1: 25 warp-tiles m16 x n64 x k64 (5 matrices x 5 m-tiles) ----
    for (int tt = warp; tt < 25; tt += 16) {
        const int mat = tt / 5, mt = tt % 5;
        const float* A  = (mat < 3) ? HS : XS;
        const float* Ab = A + mt * 16 * AST;
        const float* Wb = WT + mat * WSLOT;

        float acc[8][4];
#pragma unroll
        for (int i = 0; i < 8; ++i)
#pragma unroll
            for (int j = 0; j < 4; ++j) acc[i][j] = 0.f;

#pragma unroll
        for (int kk = 0; kk < 64; kk += 8) {
            const unsigned a0 = f2tf(Ab[g * AST + kk + tg]);
            const unsigned a1 = f2tf(Ab[(g + 8) * AST + kk + tg]);
            const unsigned a2 = f2tf(Ab[g * AST + kk + tg + 4]);
            const unsigned a3 = f2tf(Ab[(g + 8) * AST + kk + tg + 4]);
#pragma unroll
            for (int nt = 0; nt < 8; ++nt) {
                const unsigned b0 = __float_as_uint(Wb[(kk + tg) * WST + nt * 8 + g]);
                const unsigned b1 = __float_as_uint(Wb[(kk + tg + 4) * WST + nt * 8 + g]);
                mma8(acc[nt], a0, a1, a2, a3, b0, b1);
            }
        }
        // epilogue -> PRE[mat], rows < 66, conv-edge rows zeroed for q/k/v
        float* O = PRE + mat * PSLOT;
        const float* bias = BIAS + mat * 64;
        const bool qkv = (mat < 3);
        const int rA = mt * 16 + g, rB = rA + 8;
#pragma unroll
        for (int nt = 0; nt < 8; ++nt) {
            const int c0 = nt * 8 + 2 * tg;
            const float b0v = bias[c0], b1v = bias[c0 + 1];
            if (rA < 66) {
                float2 v = make_float2(acc[nt][0] + b0v, acc[nt][1] + b1v);
                if (qkv && ((zlo && rA == 0) || (zhi && rA == 65))) v = make_float2(0.f, 0.f);
                *(float2*)(O + rA * AST + c0) = v;
            }
            if (rB < 66) {
                float2 v = make_float2(acc[nt][2] + b0v, acc[nt][3] + b1v);
                if (qkv && ((zlo && rB == 0) || (zhi && rB == 65))) v = make_float2(0.f, 0.f);
                *(float2*)(O + rB * AST + c0) = v;
            }
        }
    }
    __syncthreads();

    // ---- transpose pw into WT slot 0 (tf32) ----
    for (int idx = tid; idx < 1024; idx += 512) {
        const int c = idx & 63, k4 = idx >> 6;
        const float4 w4 = *(const float4*)(pw + c * 64 + k4 * 4);
        float* dst = WT + c;
        dst[(4 * k4 + 0) * WST] = __uint_as_float(f2tf(w4.x));
        dst[(4 * k4 + 1) * WST] = __uint_as_float(f2tf(w4.y));
        dst[(4 * k4 + 2) * WST] = __uint_as_float(f2tf(w4.z));
        dst[(4 * k4 + 3) * WST] = __uint_as_float(f2tf(w4.w));
    }

    // ---- per-token stage: conv3+sigmoid+l2norm+delta+gate+zc_rmsnorm -> HS ----
    {
        const float* QP = PRE;
        const float* KP = PRE + PSLOT;
        const float* VP = PRE + 2 * PSLOT;
        const float* AP = PRE + 3 * PSLOT;
        const float* BP = PRE + 4 * PSLOT;
        const int j = 1 + warp;  // 16 warps, 4 tokens each
        for (int jj = j; jj < 65; jj += 16) {
            float qv[2], kv[2], vv[2];
#pragma unroll
            for (int h = 0; h < 2; ++h) {
                const int c = lane + 32 * h;
                const float qm = QP[(jj - 1) * AST + c], q0 = QP[jj * AST + c], qp = QP[(jj + 1) * AST + c];
                qv[h] = sigm(CW[c * 3 + 0] * qm + CW[c * 3 + 1] * q0 + CW[c * 3 + 2] * qp + CB[c]);
                const float km = KP[(jj - 1) * AST + c], k0 = KP[jj * AST + c], kp = KP[(jj + 1) * AST + c];
                kv[h] = sigm(CW[192 + c * 3 + 0] * km + CW[192 + c * 3 + 1] * k0 + CW[192 + c * 3 + 2] * kp + CB[64 + c]);
                const float vm = VP[(jj - 1) * AST + c], v0 = VP[jj * AST + c], vp = VP[(jj + 1) * AST + c];
                vv[h] = sigm(CW[384 + c * 3 + 0] * vm + CW[384 + c * 3 + 1] * v0 + CW[384 + c * 3 + 2] * vp + CB[128 + c]);
            }
            const float qi = rsqrtf(wredsum(qv[0] * qv[0] + qv[1] * qv[1]) + 1e-8f);
            const float ki = rsqrtf(wredsum(kv[0] * kv[0] + kv[1] * kv[1]) + 1e-8f);
            float d2[2];
#pragma unroll
            for (int h = 0; h < 2; ++h) {
                const int c = lane + 32 * h;
                const float delta = (qv[h] * qi) * ((kv[h] * ki) * vv[h]);
                d2[h] = tanhf(AP[jj * AST + c]) * delta + BP[jj * AST + c];
            }
            const float mean = wredsum(d2[0] + d2[1]) * (1.0f / 64.0f);
            const float e0 = d2[0] - mean, e1 = d2[1] - mean;
            const float ms = wredsum(e0 * e0 + e1 * e1) * (1.0f / 64.0f);
            const float inv = rsqrtf(ms + 1e-8f);
            HS[(jj - 1) * AST + lane]      = e0 * inv * PNG[lane];
            HS[(jj - 1) * AST + lane + 32] = e1 * inv * PNG[lane + 32];
        }
    }
    __syncthreads();

    // ---- final GEMM: 16 warp-tiles m16 x n16 x k64 + fused gating epilogue ----
    {
        const int mt  = warp >> 2;       // 0..3 (rows mt*16..mt*16+15 = tokens)
        const int nt16 = warp & 3;       // n16 chunk
        const float* Ab = HS + mt * 16 * AST;
        const float* Wb = WT;            // pw (tf32)

        float acc[2][4];
#pragma unroll
        for (int i = 0; i < 2; ++i)
#pragma unroll
            for (int j = 0; j < 4; ++j) acc[i][j] = 0.f;

#pragma unroll
        for (int kk = 0; kk < 64; kk += 8) {
            const unsigned a0 = f2tf(Ab[g * AST + kk + tg]);
            const unsigned a1 = f2tf(Ab[(g + 8) * AST + kk + tg]);
            const unsigned a2 = f2tf(Ab[g * AST + kk + tg + 4]);
            const unsigned a3 = f2tf(Ab[(g + 8) * AST + kk + tg + 4]);
#pragma unroll
            for (int nn = 0; nn < 2; ++nn) {
                const int n0 = nt16 * 16 + nn * 8;
                const unsigned b0 = __float_as_uint(Wb[(kk + tg) * WST + n0 + g]);
                const unsigned b1 = __float_as_uint(Wb[(kk + tg + 4) * WST + n0 + g]);
                mma8(acc[nn], a0, a1, a2, a3, b0, b1);
            }
        }
#pragma unroll
        for (int nn = 0; nn < 2; ++nn) {
            const int col = nt16 * 16 + nn * 8 + 2 * tg;
            const float pb0 = BIAS[320 + col], pb1 = BIAS[320 + col + 1];
#pragma unroll
            for (int h = 0; h < 2; ++h) {
                const int row = mt * 16 + g + 8 * h;     // token t0 + row
                const float d0 = acc[nn][2 * h + 0] + pb0;
                const float d1 = acc[nn][2 * h + 1] + pb1;
                const float g0 = sigm(d0 * sigm(d0));
                const float g1 = sigm(d1 * sigm(d1));
                const float2 xv = *(const float2*)(XS + (row + 1) * AST + col);
                float2 o = make_float2(xv.x + g0 * d0, xv.y + g1 * d1);
                *(float2*)(out + xbase + (long)row * 64 + col) = o;
            }
        }
    }
}

extern "C" void kernel_launch(void* const* d_in, const int* in_sizes, int n_in,
                              void* d_out, int out_size)
{
    const float* x      = (const float*)d_in[0];
    const float* norm_g = (const float*)d_in[1];
    const float* qw  = (const float*)d_in[2];
    const float* qb  = (const float*)d_in[3];
    const float* kw  = (const float*)d_in[4];
    const float* kb  = (const float*)d_in[5];
    const float* vw  = (const float*)d_in[6];
    const float* vb  = (const float*)d_in[7];
    const float* qcw = (const float*)d_in[8];
    const float* qcb = (const float*)d_in[9];
    const float* kcw = (const float*)d_in[10];
    const float* kcb = (const float*)d_in[11];
    const float* vcw = (const float*)d_in[12];
    const float* vcb = (const float*)d_in[13];
    const float* aw  = (const float*)d_in[14];
    const float* ab  = (const float*)d_in[15];
    const float* bw  = (const float*)d_in[16];
    const float* bb  = (const float*)d_in[17];
    const float* png = (const float*)d_in[18];
    const float* pw  = (const float*)d_in[19];
    const float* pb  = (const float*)d_in[20];
    float* out = (float*)d_out;

    const int smem_bytes = SMEM_FLOATS * (int)sizeof(float);
    cudaFuncSetAttribute(gdn_kernel, cudaFuncAttributeMaxDynamicSharedMemorySize, smem_bytes);
    gdn_kernel<<<4096, 512, smem_bytes>>>(
        x, norm_g, qw, qb, kw, kb, vw, vb, qcw, qcb, kcw, kcb, vcw, vcb,
        aw, ab, bw, bb, png, pw, pb, out);
}